// round 15
// baseline (speedup 1.0000x reference)
#include <cuda_runtime.h>
#include <cstdint>
#include <math.h>

#define TOKENS 8192
#define HIDDEN 7168
#define NEXP   256
#define TOP_K  8

// ---- GEMM: CTA 128x128xK896, 8 warps (2x4, warp 64x32), 2 CTAs/SM ----------
// [R9 mainloop byte-identical: zero register margin — DO NOT MODIFY]
#define BM 128
#define BN 128
#define BK 32
#define KSPLIT 8
#define KSLICE (HIDDEN / KSPLIT)    // 896
#define KT_ITERS (KSLICE / BK)      // 28
#define STAGES 3
#define NTHREADS 256
#define ASTRIDE 36                  // banks (4m+k) all distinct
#define BSTRIDE 136                 // banks (8k+n) all distinct
#define A_FLOATS (BM * ASTRIDE)     // 4608
#define B_FLOATS (BK * BSTRIDE)     // 4352
#define STAGE_FLOATS (A_FLOATS + B_FLOATS)      // 8960
#define SMEM_DYN (STAGES * STAGE_FLOATS * 4)    // 107520 B -> 2 CTAs/SM

// single accumulation buffer (zero at module load; route self-cleans)
__device__ float g_logits[(size_t)TOKENS * NEXP];

__device__ __forceinline__ uint32_t smem_u32(const void* p) {
    uint32_t a;
    asm("{ .reg .u64 t; cvta.to.shared.u64 t, %1; cvt.u32.u64 %0, t; }" : "=r"(a) : "l"(p));
    return a;
}
__device__ __forceinline__ void cp_async16(uint32_t s, const void* g) {
    asm volatile("cp.async.cg.shared.global [%0], [%1], 16;\n" :: "r"(s), "l"(g));
}
__device__ __forceinline__ void mma_tf32(float* c, const uint32_t* a, const uint32_t* b) {
    asm volatile(
        "mma.sync.aligned.m16n8k8.row.col.f32.tf32.tf32.f32 "
        "{%0,%1,%2,%3}, {%4,%5,%6,%7}, {%8,%9}, {%0,%1,%2,%3};\n"
        : "+f"(c[0]), "+f"(c[1]), "+f"(c[2]), "+f"(c[3])
        : "r"(a[0]), "r"(a[1]), "r"(a[2]), "r"(a[3]), "r"(b[0]), "r"(b[1]));
}
__device__ __forceinline__ void red_add_f32(float* p, float v) {
    asm volatile("red.global.add.f32 [%0], %1;" :: "l"(p), "f"(v) : "memory");
}

// ---------------------------------------------------------------------------
// GEMM: g_logits += A[mtile rows, kslice] * B[kslice, ntile cols]
// grid (16, 64): x = ntile + 2*ksl, y = mtile.  1024 CTAs, ~3.5 waves.
// Epilogue accumulates with RED.ADD (no return) into the shared 8 MB buffer.
// ---------------------------------------------------------------------------
__global__ __launch_bounds__(NTHREADS, 2) void gemm_kernel(
    const float* __restrict__ A, const float* __restrict__ B)
{
    extern __shared__ float smem[];

    const int tid    = threadIdx.x;
    const int wid    = tid >> 5;
    const int lane   = tid & 31;
    const int warp_m = wid >> 2;    // 0..1 -> 64 rows
    const int warp_n = wid & 3;     // 0..3 -> 32 cols
    const int ntile  = blockIdx.x & 1;
    const int ksl    = blockIdx.x >> 1;
    const int brow   = blockIdx.y * BM;
    const int bcol   = ntile * BN;
    const int kbase  = ksl * KSLICE;

    // per-thread load slots: A 1024 chunks (4/thr), B 1024 chunks (4/thr)
    const float* agp[4]; uint32_t aof[4];
    const float* bgp[4]; uint32_t bof[4];
    #pragma unroll
    for (int j = 0; j < 4; j++) {
        int i = tid + j * 256;          // A: 128 rows x 8 chunks of 16B
        int r = i >> 3, c = i & 7;
        aof[j] = (uint32_t)(r * ASTRIDE + c * 4) * 4u;
        agp[j] = A + (size_t)(brow + r) * HIDDEN + kbase + c * 4;
    }
    #pragma unroll
    for (int j = 0; j < 4; j++) {
        int i = tid + j * 256;          // B: 32 rows x 32 chunks of 16B
        int r = i >> 5, c = i & 31;
        bof[j] = (uint32_t)(A_FLOATS + r * BSTRIDE + c * 4) * 4u;
        bgp[j] = B + (size_t)(kbase + r) * NEXP + bcol + c * 4;
    }
    const uint32_t smem_base = smem_u32(smem);

    auto load_stage = [&](int kt) {
        const uint32_t sbase = smem_base + (uint32_t)(kt % STAGES) * (STAGE_FLOATS * 4);
        const int koff = kt * BK;
        #pragma unroll
        for (int j = 0; j < 4; j++) cp_async16(sbase + aof[j], agp[j] + koff);
        #pragma unroll
        for (int j = 0; j < 4; j++) cp_async16(sbase + bof[j], bgp[j] + (size_t)koff * NEXP);
        asm volatile("cp.async.commit_group;\n" ::: "memory");
    };

    float acc[4][4][4];
    #pragma unroll
    for (int mt = 0; mt < 4; mt++)
        #pragma unroll
        for (int nt = 0; nt < 4; nt++)
            #pragma unroll
            for (int i = 0; i < 4; i++) acc[mt][nt][i] = 0.f;

    load_stage(0);
    load_stage(1);

    const int arow0 = warp_m * 64 + (lane >> 2);
    const int bcol0 = warp_n * 32 + (lane >> 2);
    const int ak    = lane & 3;

    for (int kt = 0; kt < KT_ITERS; kt++) {
        if (kt == KT_ITERS - 1)
            asm volatile("cp.async.wait_group 0;\n" ::: "memory");
        else
            asm volatile("cp.async.wait_group 1;\n" ::: "memory");
        __syncthreads();      // single barrier per kt (also guards buffer reuse)

        if (kt + 2 < KT_ITERS) load_stage(kt + 2);

        const float* As = smem + (size_t)(kt % STAGES) * STAGE_FLOATS;
        const float* Bs = As + A_FLOATS;

        #pragma unroll
        for (int ks = 0; ks < 4; ks++) {
            const int kk = ks * 8;
            uint32_t afr[4][4];
            uint32_t bfr[4][2];
            #pragma unroll
            for (int mt = 0; mt < 4; mt++) {
                const int m0 = arow0 + mt * 16;
                const int cc = kk + ak;
                afr[mt][0] = __float_as_uint(As[m0 * ASTRIDE + cc]);
                afr[mt][1] = __float_as_uint(As[(m0 + 8) * ASTRIDE + cc]);
                afr[mt][2] = __float_as_uint(As[m0 * ASTRIDE + cc + 4]);
                afr[mt][3] = __float_as_uint(As[(m0 + 8) * ASTRIDE + cc + 4]);
            }
            #pragma unroll
            for (int nt = 0; nt < 4; nt++) {
                const int n0 = bcol0 + nt * 8;
                const int kr = kk + ak;
                bfr[nt][0] = __float_as_uint(Bs[kr * BSTRIDE + n0]);
                bfr[nt][1] = __float_as_uint(Bs[(kr + 4) * BSTRIDE + n0]);
            }
            #pragma unroll
            for (int mt = 0; mt < 4; mt++)
                #pragma unroll
                for (int nt = 0; nt < 4; nt++)
                    mma_tf32(acc[mt][nt], afr[mt], bfr[nt]);
        }
    }

    // epilogue: accumulate into the single logits buffer (RED, no return).
    // Same addressing as the R9 store epilogue; no new computed values.
    #pragma unroll
    for (int mt = 0; mt < 4; mt++) {
        #pragma unroll
        for (int nt = 0; nt < 4; nt++) {
            int row = brow + warp_m * 64 + mt * 16 + (lane >> 2);
            int col = bcol + warp_n * 32 + nt * 8 + (lane & 3) * 2;
            float* p0 = &g_logits[(size_t)row * NEXP + col];
            float* p1 = &g_logits[(size_t)(row + 8) * NEXP + col];
            red_add_f32(p0,     acc[mt][nt][0]);
            red_add_f32(p0 + 1, acc[mt][nt][1]);
            red_add_f32(p1,     acc[mt][nt][2]);
            red_add_f32(p1 + 1, acc[mt][nt][3]);
        }
    }
}

// ---------------------------------------------------------------------------
// Routing: read summed logits (8 MB), MUFU sigmoid + bias, group top-2 sums,
// top-4 groups, top-8 experts, renormalize * 2.5. One warp per token.
// Self-cleans g_logits (zeroes what it read) for the next graph replay.
// ---------------------------------------------------------------------------
__global__ __launch_bounds__(256) void route_kernel(
    const float* __restrict__ bias, float* __restrict__ out)
{
    const int lane  = threadIdx.x & 31;
    const int token = blockIdx.x * 8 + (threadIdx.x >> 5);
    if (token >= TOKENS) return;

    float bias_r[8];
    #pragma unroll
    for (int i = 0; i < 8; i++) bias_r[i] = __ldg(&bias[lane * 8 + i]);

    float4* prow = (float4*)(g_logits + (size_t)token * NEXP + lane * 8);
    float4 x = prow[0], y = prow[1];
    float l[8] = { x.x, x.y, x.z, x.w, y.x, y.y, y.z, y.w };

    // self-clean for the next replay (buffer is accumulate-in-place)
    prow[0] = make_float4(0.f, 0.f, 0.f, 0.f);
    prow[1] = make_float4(0.f, 0.f, 0.f, 0.f);

    float s[8];
    #pragma unroll
    for (int i = 0; i < 8; i++) {
        float sc = 1.f / (1.f + __expf(-l[i]));
        s[i] = sc + bias_r[i];
    }

    float m1 = -INFINITY, m2 = -INFINITY;
    #pragma unroll
    for (int i = 0; i < 8; i++) {
        float v = s[i];
        if (v > m1) { m2 = m1; m1 = v; }
        else if (v > m2) { m2 = v; }
    }
    #pragma unroll
    for (int off = 1; off <= 2; off <<= 1) {
        float o1 = __shfl_xor_sync(0xffffffffu, m1, off);
        float o2 = __shfl_xor_sync(0xffffffffu, m2, off);
        float hi = fmaxf(m1, o1);
        float lo = fmaxf(fminf(m1, o1), fmaxf(m2, o2));
        m1 = hi; m2 = lo;
    }
    float gsum = m1 + m2;

    float gs[8];
    #pragma unroll
    for (int g = 0; g < 8; g++)
        gs[g] = __shfl_sync(0xffffffffu, gsum, g * 4);

    const int myg = lane >> 2;
    int rank = 0;
    #pragma unroll
    for (int h = 0; h < 8; h++)
        if (gs[h] > gs[myg] || (gs[h] == gs[myg] && h < myg)) rank++;
    const bool sel = rank < 4;

    float vals[8];
    #pragma unroll
    for (int i = 0; i < 8; i++) vals[i] = sel ? s[i] : 0.f;

    float w[TOP_K];
    #pragma unroll
    for (int t = 0; t < TOP_K; t++) {
        float bv = vals[0];
        int bi = 0;
        #pragma unroll
        for (int i = 1; i < 8; i++)
            if (vals[i] > bv) { bv = vals[i]; bi = i; }
        int bidx = lane * 8 + bi;
        #pragma unroll
        for (int off = 16; off >= 1; off >>= 1) {
            float ov = __shfl_xor_sync(0xffffffffu, bv, off);
            int   oi = __shfl_xor_sync(0xffffffffu, bidx, off);
            if (ov > bv || (ov == bv && oi < bidx)) { bv = ov; bidx = oi; }
        }
        w[t] = bv;
        if ((bidx >> 3) == lane) vals[bidx & 7] = -INFINITY;
    }

    float denom = 1e-20f;
    #pragma unroll
    for (int t = 0; t < TOP_K; t++) denom += w[t];
    const float scale = 2.5f / denom;

    if (lane == 0) {
        #pragma unroll
        for (int t = 0; t < TOP_K; t++)
            out[(size_t)token * TOP_K + t] = w[t] * scale;
    }
}

// ---------------------------------------------------------------------------
extern "C" void kernel_launch(void* const* d_in, const int* in_sizes, int n_in,
                              void* d_out, int out_size)
{
    (void)in_sizes; (void)n_in; (void)out_size;
    const float* hs   = (const float*)d_in[0];  // [8192, 7168]
    const float* W    = (const float*)d_in[1];  // [7168, 256]
    const float* bias = (const float*)d_in[2];  // [256]
    float* out = (float*)d_out;                 // [8192, 8]

    cudaFuncSetAttribute(gemm_kernel, cudaFuncAttributeMaxDynamicSharedMemorySize, SMEM_DYN);

    dim3 grid(2 * KSPLIT, TOKENS / BM);         // (16, 64) = 1024 CTAs
    gemm_kernel<<<grid, NTHREADS, SMEM_DYN>>>(hs, W);
    route_kernel<<<TOKENS / 8, 256>>>(bias, out);
}

// round 16
// speedup vs baseline: 1.0170x; 1.0170x over previous
#include <cuda_runtime.h>
#include <cstdint>
#include <math.h>

#define TOKENS 8192
#define HIDDEN 7168
#define NEXP   256
#define TOP_K  8

// ---- GEMM: CTA 128x128xK896, 8 warps (2x4, warp 64x32), 2 CTAs/SM ----------
// [R9 mainloop byte-identical: zero register margin — DO NOT MODIFY]
#define BM 128
#define BN 128
#define BK 32
#define KSPLIT 8
#define KSLICE (HIDDEN / KSPLIT)    // 896
#define KT_ITERS (KSLICE / BK)      // 28
#define STAGES 3
#define NTHREADS 256
#define ASTRIDE 36                  // banks (4m+k) all distinct
#define BSTRIDE 136                 // banks (8k+n) all distinct
#define A_FLOATS (BM * ASTRIDE)     // 4608
#define B_FLOATS (BK * BSTRIDE)     // 4352
#define STAGE_FLOATS (A_FLOATS + B_FLOATS)      // 8960
#define SMEM_DYN (STAGES * STAGE_FLOATS * 4)    // 107520 B -> 2 CTAs/SM

// single accumulation buffer (zero at module load; route self-cleans)
__device__ float g_logits[(size_t)TOKENS * NEXP];

__device__ __forceinline__ uint32_t smem_u32(const void* p) {
    uint32_t a;
    asm("{ .reg .u64 t; cvta.to.shared.u64 t, %1; cvt.u32.u64 %0, t; }" : "=r"(a) : "l"(p));
    return a;
}
__device__ __forceinline__ void cp_async16(uint32_t s, const void* g) {
    asm volatile("cp.async.cg.shared.global [%0], [%1], 16;\n" :: "r"(s), "l"(g));
}
__device__ __forceinline__ void mma_tf32(float* c, const uint32_t* a, const uint32_t* b) {
    asm volatile(
        "mma.sync.aligned.m16n8k8.row.col.f32.tf32.tf32.f32 "
        "{%0,%1,%2,%3}, {%4,%5,%6,%7}, {%8,%9}, {%0,%1,%2,%3};\n"
        : "+f"(c[0]), "+f"(c[1]), "+f"(c[2]), "+f"(c[3])
        : "r"(a[0]), "r"(a[1]), "r"(a[2]), "r"(a[3]), "r"(b[0]), "r"(b[1]));
}
// vector reduction: one L2 op per float2 (sm_90+ PTX vector red)
__device__ __forceinline__ void red_add_v2(float* p, float a, float b) {
    asm volatile("red.global.add.v2.f32 [%0], {%1, %2};"
                 :: "l"(p), "f"(a), "f"(b) : "memory");
}

// ---------------------------------------------------------------------------
// GEMM: g_logits += A[mtile rows, kslice] * B[kslice, ntile cols]
// grid (16, 64): x = ntile + 2*ksl, y = mtile.  1024 CTAs, ~3.5 waves.
// Epilogue accumulates with RED.v2 (no return) into the shared 8 MB buffer —
// same op count and addresses as the R14 float2 stores.
// ---------------------------------------------------------------------------
__global__ __launch_bounds__(NTHREADS, 2) void gemm_kernel(
    const float* __restrict__ A, const float* __restrict__ B)
{
    extern __shared__ float smem[];

    const int tid    = threadIdx.x;
    const int wid    = tid >> 5;
    const int lane   = tid & 31;
    const int warp_m = wid >> 2;    // 0..1 -> 64 rows
    const int warp_n = wid & 3;     // 0..3 -> 32 cols
    const int ntile  = blockIdx.x & 1;
    const int ksl    = blockIdx.x >> 1;
    const int brow   = blockIdx.y * BM;
    const int bcol   = ntile * BN;
    const int kbase  = ksl * KSLICE;

    // per-thread load slots: A 1024 chunks (4/thr), B 1024 chunks (4/thr)
    const float* agp[4]; uint32_t aof[4];
    const float* bgp[4]; uint32_t bof[4];
    #pragma unroll
    for (int j = 0; j < 4; j++) {
        int i = tid + j * 256;          // A: 128 rows x 8 chunks of 16B
        int r = i >> 3, c = i & 7;
        aof[j] = (uint32_t)(r * ASTRIDE + c * 4) * 4u;
        agp[j] = A + (size_t)(brow + r) * HIDDEN + kbase + c * 4;
    }
    #pragma unroll
    for (int j = 0; j < 4; j++) {
        int i = tid + j * 256;          // B: 32 rows x 32 chunks of 16B
        int r = i >> 5, c = i & 31;
        bof[j] = (uint32_t)(A_FLOATS + r * BSTRIDE + c * 4) * 4u;
        bgp[j] = B + (size_t)(kbase + r) * NEXP + bcol + c * 4;
    }
    const uint32_t smem_base = smem_u32(smem);

    auto load_stage = [&](int kt) {
        const uint32_t sbase = smem_base + (uint32_t)(kt % STAGES) * (STAGE_FLOATS * 4);
        const int koff = kt * BK;
        #pragma unroll
        for (int j = 0; j < 4; j++) cp_async16(sbase + aof[j], agp[j] + koff);
        #pragma unroll
        for (int j = 0; j < 4; j++) cp_async16(sbase + bof[j], bgp[j] + (size_t)koff * NEXP);
        asm volatile("cp.async.commit_group;\n" ::: "memory");
    };

    float acc[4][4][4];
    #pragma unroll
    for (int mt = 0; mt < 4; mt++)
        #pragma unroll
        for (int nt = 0; nt < 4; nt++)
            #pragma unroll
            for (int i = 0; i < 4; i++) acc[mt][nt][i] = 0.f;

    load_stage(0);
    load_stage(1);

    const int arow0 = warp_m * 64 + (lane >> 2);
    const int bcol0 = warp_n * 32 + (lane >> 2);
    const int ak    = lane & 3;

    for (int kt = 0; kt < KT_ITERS; kt++) {
        if (kt == KT_ITERS - 1)
            asm volatile("cp.async.wait_group 0;\n" ::: "memory");
        else
            asm volatile("cp.async.wait_group 1;\n" ::: "memory");
        __syncthreads();      // single barrier per kt (also guards buffer reuse)

        if (kt + 2 < KT_ITERS) load_stage(kt + 2);

        const float* As = smem + (size_t)(kt % STAGES) * STAGE_FLOATS;
        const float* Bs = As + A_FLOATS;

        #pragma unroll
        for (int ks = 0; ks < 4; ks++) {
            const int kk = ks * 8;
            uint32_t afr[4][4];
            uint32_t bfr[4][2];
            #pragma unroll
            for (int mt = 0; mt < 4; mt++) {
                const int m0 = arow0 + mt * 16;
                const int cc = kk + ak;
                afr[mt][0] = __float_as_uint(As[m0 * ASTRIDE + cc]);
                afr[mt][1] = __float_as_uint(As[(m0 + 8) * ASTRIDE + cc]);
                afr[mt][2] = __float_as_uint(As[m0 * ASTRIDE + cc + 4]);
                afr[mt][3] = __float_as_uint(As[(m0 + 8) * ASTRIDE + cc + 4]);
            }
            #pragma unroll
            for (int nt = 0; nt < 4; nt++) {
                const int n0 = bcol0 + nt * 8;
                const int kr = kk + ak;
                bfr[nt][0] = __float_as_uint(Bs[kr * BSTRIDE + n0]);
                bfr[nt][1] = __float_as_uint(Bs[(kr + 4) * BSTRIDE + n0]);
            }
            #pragma unroll
            for (int mt = 0; mt < 4; mt++)
                #pragma unroll
                for (int nt = 0; nt < 4; nt++)
                    mma_tf32(acc[mt][nt], afr[mt], bfr[nt]);
        }
    }

    // epilogue: accumulate into the single logits buffer (vector RED, no
    // return). Same op count/addresses as the R14 float2-store epilogue.
    #pragma unroll
    for (int mt = 0; mt < 4; mt++) {
        #pragma unroll
        for (int nt = 0; nt < 4; nt++) {
            int row = brow + warp_m * 64 + mt * 16 + (lane >> 2);
            int col = bcol + warp_n * 32 + nt * 8 + (lane & 3) * 2;
            red_add_v2(&g_logits[(size_t)row * NEXP + col],
                       acc[mt][nt][0], acc[mt][nt][1]);
            red_add_v2(&g_logits[(size_t)(row + 8) * NEXP + col],
                       acc[mt][nt][2], acc[mt][nt][3]);
        }
    }
}

// ---------------------------------------------------------------------------
// Routing: read summed logits (8 MB), MUFU sigmoid + bias, group top-2 sums,
// top-4 groups, top-8 experts, renormalize * 2.5. One warp per token.
// Self-cleans g_logits (zeroes what it read) for the next graph replay.
// ---------------------------------------------------------------------------
__global__ __launch_bounds__(256) void route_kernel(
    const float* __restrict__ bias, float* __restrict__ out)
{
    const int lane  = threadIdx.x & 31;
    const int token = blockIdx.x * 8 + (threadIdx.x >> 5);
    if (token >= TOKENS) return;

    float bias_r[8];
    #pragma unroll
    for (int i = 0; i < 8; i++) bias_r[i] = __ldg(&bias[lane * 8 + i]);

    float4* prow = (float4*)(g_logits + (size_t)token * NEXP + lane * 8);
    float4 x = prow[0], y = prow[1];
    float l[8] = { x.x, x.y, x.z, x.w, y.x, y.y, y.z, y.w };

    // self-clean for the next replay (buffer is accumulate-in-place)
    prow[0] = make_float4(0.f, 0.f, 0.f, 0.f);
    prow[1] = make_float4(0.f, 0.f, 0.f, 0.f);

    float s[8];
    #pragma unroll
    for (int i = 0; i < 8; i++) {
        float sc = 1.f / (1.f + __expf(-l[i]));
        s[i] = sc + bias_r[i];
    }

    float m1 = -INFINITY, m2 = -INFINITY;
    #pragma unroll
    for (int i = 0; i < 8; i++) {
        float v = s[i];
        if (v > m1) { m2 = m1; m1 = v; }
        else if (v > m2) { m2 = v; }
    }
    #pragma unroll
    for (int off = 1; off <= 2; off <<= 1) {
        float o1 = __shfl_xor_sync(0xffffffffu, m1, off);
        float o2 = __shfl_xor_sync(0xffffffffu, m2, off);
        float hi = fmaxf(m1, o1);
        float lo = fmaxf(fminf(m1, o1), fmaxf(m2, o2));
        m1 = hi; m2 = lo;
    }
    float gsum = m1 + m2;

    float gs[8];
    #pragma unroll
    for (int g = 0; g < 8; g++)
        gs[g] = __shfl_sync(0xffffffffu, gsum, g * 4);

    const int myg = lane >> 2;
    int rank = 0;
    #pragma unroll
    for (int h = 0; h < 8; h++)
        if (gs[h] > gs[myg] || (gs[h] == gs[myg] && h < myg)) rank++;
    const bool sel = rank < 4;

    float vals[8];
    #pragma unroll
    for (int i = 0; i < 8; i++) vals[i] = sel ? s[i] : 0.f;

    float w[TOP_K];
    #pragma unroll
    for (int t = 0; t < TOP_K; t++) {
        float bv = vals[0];
        int bi = 0;
        #pragma unroll
        for (int i = 1; i < 8; i++)
            if (vals[i] > bv) { bv = vals[i]; bi = i; }
        int bidx = lane * 8 + bi;
        #pragma unroll
        for (int off = 16; off >= 1; off >>= 1) {
            float ov = __shfl_xor_sync(0xffffffffu, bv, off);
            int   oi = __shfl_xor_sync(0xffffffffu, bidx, off);
            if (ov > bv || (ov == bv && oi < bidx)) { bv = ov; bidx = oi; }
        }
        w[t] = bv;
        if ((bidx >> 3) == lane) vals[bidx & 7] = -INFINITY;
    }

    float denom = 1e-20f;
    #pragma unroll
    for (int t = 0; t < TOP_K; t++) denom += w[t];
    const float scale = 2.5f / denom;

    if (lane == 0) {
        #pragma unroll
        for (int t = 0; t < TOP_K; t++)
            out[(size_t)token * TOP_K + t] = w[t] * scale;
    }
}

// ---------------------------------------------------------------------------
extern "C" void kernel_launch(void* const* d_in, const int* in_sizes, int n_in,
                              void* d_out, int out_size)
{
    (void)in_sizes; (void)n_in; (void)out_size;
    const float* hs   = (const float*)d_in[0];  // [8192, 7168]
    const float* W    = (const float*)d_in[1];  // [7168, 256]
    const float* bias = (const float*)d_in[2];  // [256]
    float* out = (float*)d_out;                 // [8192, 8]

    cudaFuncSetAttribute(gemm_kernel, cudaFuncAttributeMaxDynamicSharedMemorySize, SMEM_DYN);

    dim3 grid(2 * KSPLIT, TOKENS / BM);         // (16, 64) = 1024 CTAs
    gemm_kernel<<<grid, NTHREADS, SMEM_DYN>>>(hs, W);
    route_kernel<<<TOKENS / 8, 256>>>(bias, out);
}

// round 17
// speedup vs baseline: 1.0314x; 1.0142x over previous
#include <cuda_runtime.h>
#include <cstdint>
#include <math.h>

#define TOKENS 8192
#define HIDDEN 7168
#define NEXP   256
#define TOP_K  8

// ---- GEMM: CTA 128x128xK896, 8 warps (2x4, warp 64x32), 2 CTAs/SM ----------
// [R9 mainloop byte-identical: zero register margin — DO NOT MODIFY]
#define BM 128
#define BN 128
#define BK 32
#define KSPLIT 8
#define KSLICE (HIDDEN / KSPLIT)    // 896
#define KT_ITERS (KSLICE / BK)      // 28
#define STAGES 3
#define NTHREADS 256
#define ASTRIDE 36                  // banks (4m+k) all distinct
#define BSTRIDE 136                 // banks (8k+n) all distinct
#define A_FLOATS (BM * ASTRIDE)     // 4608
#define B_FLOATS (BK * BSTRIDE)     // 4352
#define STAGE_FLOATS (A_FLOATS + B_FLOATS)      // 8960
#define SMEM_DYN (STAGES * STAGE_FLOATS * 4)    // 107520 B -> 2 CTAs/SM

// single accumulation buffer (zero at module load; route self-cleans)
__device__ float g_logits[(size_t)TOKENS * NEXP];

__device__ __forceinline__ uint32_t smem_u32(const void* p) {
    uint32_t a;
    asm("{ .reg .u64 t; cvta.to.shared.u64 t, %1; cvt.u32.u64 %0, t; }" : "=r"(a) : "l"(p));
    return a;
}
__device__ __forceinline__ void cp_async16(uint32_t s, const void* g) {
    asm volatile("cp.async.cg.shared.global [%0], [%1], 16;\n" :: "r"(s), "l"(g));
}
__device__ __forceinline__ void mma_tf32(float* c, const uint32_t* a, const uint32_t* b) {
    asm volatile(
        "mma.sync.aligned.m16n8k8.row.col.f32.tf32.tf32.f32 "
        "{%0,%1,%2,%3}, {%4,%5,%6,%7}, {%8,%9}, {%0,%1,%2,%3};\n"
        : "+f"(c[0]), "+f"(c[1]), "+f"(c[2]), "+f"(c[3])
        : "r"(a[0]), "r"(a[1]), "r"(a[2]), "r"(a[3]), "r"(b[0]), "r"(b[1]));
}
// vector reduction: one L2 op per float2 (sm_90+ PTX vector red)
__device__ __forceinline__ void red_add_v2(float* p, float a, float b) {
    asm volatile("red.global.add.v2.f32 [%0], {%1, %2};"
                 :: "l"(p), "f"(a), "f"(b) : "memory");
}
// order-preserving float->uint key (and exact inverse)
__device__ __forceinline__ unsigned ord_key(float f) {
    unsigned b = __float_as_uint(f);
    return (b & 0x80000000u) ? ~b : (b | 0x80000000u);
}
__device__ __forceinline__ float ord_inv(unsigned u) {
    unsigned b = (u & 0x80000000u) ? (u & 0x7fffffffu) : ~u;
    return __uint_as_float(b);
}

// ---------------------------------------------------------------------------
// GEMM: g_logits += A[mtile rows, kslice] * B[kslice, ntile cols]
// grid (16, 64): x = ntile + 2*ksl, y = mtile.  1024 CTAs, ~3.5 waves.
// Epilogue accumulates with RED.v2 (no return) into the shared 8 MB buffer.
// ---------------------------------------------------------------------------
__global__ __launch_bounds__(NTHREADS, 2) void gemm_kernel(
    const float* __restrict__ A, const float* __restrict__ B)
{
    extern __shared__ float smem[];

    const int tid    = threadIdx.x;
    const int wid    = tid >> 5;
    const int lane   = tid & 31;
    const int warp_m = wid >> 2;    // 0..1 -> 64 rows
    const int warp_n = wid & 3;     // 0..3 -> 32 cols
    const int ntile  = blockIdx.x & 1;
    const int ksl    = blockIdx.x >> 1;
    const int brow   = blockIdx.y * BM;
    const int bcol   = ntile * BN;
    const int kbase  = ksl * KSLICE;

    // per-thread load slots: A 1024 chunks (4/thr), B 1024 chunks (4/thr)
    const float* agp[4]; uint32_t aof[4];
    const float* bgp[4]; uint32_t bof[4];
    #pragma unroll
    for (int j = 0; j < 4; j++) {
        int i = tid + j * 256;          // A: 128 rows x 8 chunks of 16B
        int r = i >> 3, c = i & 7;
        aof[j] = (uint32_t)(r * ASTRIDE + c * 4) * 4u;
        agp[j] = A + (size_t)(brow + r) * HIDDEN + kbase + c * 4;
    }
    #pragma unroll
    for (int j = 0; j < 4; j++) {
        int i = tid + j * 256;          // B: 32 rows x 32 chunks of 16B
        int r = i >> 5, c = i & 31;
        bof[j] = (uint32_t)(A_FLOATS + r * BSTRIDE + c * 4) * 4u;
        bgp[j] = B + (size_t)(kbase + r) * NEXP + bcol + c * 4;
    }
    const uint32_t smem_base = smem_u32(smem);

    auto load_stage = [&](int kt) {
        const uint32_t sbase = smem_base + (uint32_t)(kt % STAGES) * (STAGE_FLOATS * 4);
        const int koff = kt * BK;
        #pragma unroll
        for (int j = 0; j < 4; j++) cp_async16(sbase + aof[j], agp[j] + koff);
        #pragma unroll
        for (int j = 0; j < 4; j++) cp_async16(sbase + bof[j], bgp[j] + (size_t)koff * NEXP);
        asm volatile("cp.async.commit_group;\n" ::: "memory");
    };

    float acc[4][4][4];
    #pragma unroll
    for (int mt = 0; mt < 4; mt++)
        #pragma unroll
        for (int nt = 0; nt < 4; nt++)
            #pragma unroll
            for (int i = 0; i < 4; i++) acc[mt][nt][i] = 0.f;

    load_stage(0);
    load_stage(1);

    const int arow0 = warp_m * 64 + (lane >> 2);
    const int bcol0 = warp_n * 32 + (lane >> 2);
    const int ak    = lane & 3;

    for (int kt = 0; kt < KT_ITERS; kt++) {
        if (kt == KT_ITERS - 1)
            asm volatile("cp.async.wait_group 0;\n" ::: "memory");
        else
            asm volatile("cp.async.wait_group 1;\n" ::: "memory");
        __syncthreads();      // single barrier per kt (also guards buffer reuse)

        if (kt + 2 < KT_ITERS) load_stage(kt + 2);

        const float* As = smem + (size_t)(kt % STAGES) * STAGE_FLOATS;
        const float* Bs = As + A_FLOATS;

        #pragma unroll
        for (int ks = 0; ks < 4; ks++) {
            const int kk = ks * 8;
            uint32_t afr[4][4];
            uint32_t bfr[4][2];
            #pragma unroll
            for (int mt = 0; mt < 4; mt++) {
                const int m0 = arow0 + mt * 16;
                const int cc = kk + ak;
                afr[mt][0] = __float_as_uint(As[m0 * ASTRIDE + cc]);
                afr[mt][1] = __float_as_uint(As[(m0 + 8) * ASTRIDE + cc]);
                afr[mt][2] = __float_as_uint(As[m0 * ASTRIDE + cc + 4]);
                afr[mt][3] = __float_as_uint(As[(m0 + 8) * ASTRIDE + cc + 4]);
            }
            #pragma unroll
            for (int nt = 0; nt < 4; nt++) {
                const int n0 = bcol0 + nt * 8;
                const int kr = kk + ak;
                bfr[nt][0] = __float_as_uint(Bs[kr * BSTRIDE + n0]);
                bfr[nt][1] = __float_as_uint(Bs[(kr + 4) * BSTRIDE + n0]);
            }
            #pragma unroll
            for (int mt = 0; mt < 4; mt++)
                #pragma unroll
                for (int nt = 0; nt < 4; nt++)
                    mma_tf32(acc[mt][nt], afr[mt], bfr[nt]);
        }
    }

    // epilogue: accumulate into the single logits buffer (vector RED).
    #pragma unroll
    for (int mt = 0; mt < 4; mt++) {
        #pragma unroll
        for (int nt = 0; nt < 4; nt++) {
            int row = brow + warp_m * 64 + mt * 16 + (lane >> 2);
            int col = bcol + warp_n * 32 + nt * 8 + (lane & 3) * 2;
            red_add_v2(&g_logits[(size_t)row * NEXP + col],
                       acc[mt][nt][0], acc[mt][nt][1]);
            red_add_v2(&g_logits[(size_t)(row + 8) * NEXP + col],
                       acc[mt][nt][2], acc[mt][nt][3]);
        }
    }
}

// ---------------------------------------------------------------------------
// Routing: read summed logits (8 MB), MUFU sigmoid + bias, group top-2 sums,
// top-4 groups, REDUX-based top-8 experts, renormalize * 2.5. One warp/token.
// Self-cleans g_logits for the next graph replay.
// ---------------------------------------------------------------------------
__global__ __launch_bounds__(256) void route_kernel(
    const float* __restrict__ bias, float* __restrict__ out)
{
    const int lane  = threadIdx.x & 31;
    const int token = blockIdx.x * 8 + (threadIdx.x >> 5);
    if (token >= TOKENS) return;

    float bias_r[8];
    #pragma unroll
    for (int i = 0; i < 8; i++) bias_r[i] = __ldg(&bias[lane * 8 + i]);

    float4* prow = (float4*)(g_logits + (size_t)token * NEXP + lane * 8);
    float4 x = prow[0], y = prow[1];
    float l[8] = { x.x, x.y, x.z, x.w, y.x, y.y, y.z, y.w };

    // self-clean for the next replay (buffer is accumulate-in-place)
    prow[0] = make_float4(0.f, 0.f, 0.f, 0.f);
    prow[1] = make_float4(0.f, 0.f, 0.f, 0.f);

    float s[8];
    #pragma unroll
    for (int i = 0; i < 8; i++) {
        float sc = 1.f / (1.f + __expf(-l[i]));
        s[i] = sc + bias_r[i];
    }

    // group top-2 (per-lane top-2, merged across the 4 lanes of the group)
    float m1 = -INFINITY, m2 = -INFINITY;
    #pragma unroll
    for (int i = 0; i < 8; i++) {
        float v = s[i];
        if (v > m1) { m2 = m1; m1 = v; }
        else if (v > m2) { m2 = v; }
    }
    #pragma unroll
    for (int off = 1; off <= 2; off <<= 1) {
        float o1 = __shfl_xor_sync(0xffffffffu, m1, off);
        float o2 = __shfl_xor_sync(0xffffffffu, m2, off);
        float hi = fmaxf(m1, o1);
        float lo = fmaxf(fminf(m1, o1), fmaxf(m2, o2));
        m1 = hi; m2 = lo;
    }
    float gsum = m1 + m2;

    float gs[8];
    #pragma unroll
    for (int g = 0; g < 8; g++)
        gs[g] = __shfl_sync(0xffffffffu, gsum, g * 4);

    const int myg = lane >> 2;
    int rank = 0;
    #pragma unroll
    for (int h = 0; h < 8; h++)
        if (gs[h] > gs[myg] || (gs[h] == gs[myg] && h < myg)) rank++;
    const bool sel = rank < 4;

    // keys: order-preserving uints; unselected/consumed -> 0 (below all)
    unsigned keys[8];
    #pragma unroll
    for (int i = 0; i < 8; i++)
        keys[i] = sel ? ord_key(s[i]) : ord_key(0.0f) * (unsigned)sel;
    // note: unselected lanes contribute score 0.0 in the reference's masked
    // array; encode that exactly:
    #pragma unroll
    for (int i = 0; i < 8; i++)
        keys[i] = sel ? ord_key(s[i]) : ord_key(0.0f);

    // REDUX-based top-8: per-lane scan -> warp reduce_max -> ballot owner
    float w[TOP_K];
    #pragma unroll
    for (int t = 0; t < TOP_K; t++) {
        unsigned bk = keys[0];
        int bi = 0;
        #pragma unroll
        for (int i = 1; i < 8; i++)
            if (keys[i] > bk) { bk = keys[i]; bi = i; }   // lowest i wins ties
        unsigned kmax = __reduce_max_sync(0xffffffffu, bk);
        w[t] = ord_inv(kmax);                              // exact value
        unsigned owners = __ballot_sync(0xffffffffu, bk == kmax);
        int src = __ffs(owners) - 1;                       // lowest lane wins ties
        if (lane == src) keys[bi] = 0u;                    // consume
    }

    float denom = 1e-20f;
    #pragma unroll
    for (int t = 0; t < TOP_K; t++) denom += w[t];
    const float scale = 2.5f / denom;

    if (lane == 0) {
        #pragma unroll
        for (int t = 0; t < TOP_K; t++)
            out[(size_t)token * TOP_K + t] = w[t] * scale;
    }
}

// ---------------------------------------------------------------------------
extern "C" void kernel_launch(void* const* d_in, const int* in_sizes, int n_in,
                              void* d_out, int out_size)
{
    (void)in_sizes; (void)n_in; (void)out_size;
    const float* hs   = (const float*)d_in[0];  // [8192, 7168]
    const float* W    = (const float*)d_in[1];  // [7168, 256]
    const float* bias = (const float*)d_in[2];  // [256]
    float* out = (float*)d_out;                 // [8192, 8]

    cudaFuncSetAttribute(gemm_kernel, cudaFuncAttributeMaxDynamicSharedMemorySize, SMEM_DYN);

    dim3 grid(2 * KSPLIT, TOKENS / BM);         // (16, 64) = 1024 CTAs
    gemm_kernel<<<grid, NTHREADS, SMEM_DYN>>>(hs, W);
    route_kernel<<<TOKENS / 8, 256>>>(bias, out);
}